// round 6
// baseline (speedup 1.0000x reference)
#include <cuda_runtime.h>
#include <cuda_bf16.h>

// LabelClusterLoss over E[C0=512, T=128, C1=1024] fp32 -> scalar, one launch.
// Accumulators: A_sq = sum(E^2); A_R2 = sum_rows(rowsum^2);
//               A_C2 = sum_cols(colsum^2); A_T2 = sum_t(slicesum^2).
//
// Grid = 1024 blocks x 128 thr: block b -> (t = b>>3, seg = b&7, rows seg*64..+63).
// 8 blocks/SM (64 regs exact) -> 1024/148 = 6.92 work units/SM, 1.2% imbalance.
// Last-of-8 finisher per t combines staged colsum partials; last of 128
// combiners computes the loss. No spin-waits; counters self-reset each run ->
// deterministic across graph replays. No allocations.

#define T_DIM 128
#define C0_DIM 512
#define C1_DIM 1024
#define NSEG 8
#define NBLK (T_DIM * NSEG)

__device__ float         g_cs[NBLK][C1_DIM];   // per-(t,seg) colsum partials (4 MB)
__device__ float         g_sr[NBLK][2];        // per-(t,seg) {sq, r2}
__device__ double        g_t4[T_DIM][4];       // per-t {sq, r2, cs2, cs^2}
__device__ unsigned int  g_tcnt[T_DIM];        // zero at load; self-reset
__device__ unsigned int  g_gcnt;               // zero at load; self-reset

__global__ void __launch_bounds__(128, 8)
lcl_kernel(const float* __restrict__ A, float* __restrict__ out) {
    const int b    = blockIdx.x;
    const int t    = b >> 3;
    const int seg  = b & 7;
    const int tid  = threadIdx.x;
    const int w    = tid >> 5;          // 0..3
    const int lane = tid & 31;

    __shared__ float sbuf[2 * 1024];    // 8 KB colsum staging
    __shared__ float red_a[4];
    __shared__ float red_b[4];
    __shared__ bool  s_comb;
    __shared__ bool  s_final;

    // ================= streaming pass: 64 rows of slice t =================
    float cs0[16], cs1[16];             // colsum for owned 32 columns
#pragma unroll
    for (int q = 0; q < 16; q++) { cs0[q] = 0.0f; cs1[q] = 0.0f; }
    float sq_acc = 0.0f;
    float r2_acc = 0.0f;                // lane 0 holds rowsum^2 partial

    const int row_base = seg * 64 + w;
    for (int k = 0; k < 16; k++) {
        const int i = row_base + 4 * k;
        const float4* row =
            reinterpret_cast<const float4*>(A + ((size_t)i * T_DIM + t) * C1_DIM) + lane;
        float rs = 0.0f;
#pragma unroll
        for (int p = 0; p < 8; p++) {
            float4 v = __ldcs(row + p * 32);   // 512B/warp contiguous
            sq_acc = fmaf(v.x, v.x, sq_acc);
            sq_acc = fmaf(v.y, v.y, sq_acc);
            sq_acc = fmaf(v.z, v.z, sq_acc);
            sq_acc = fmaf(v.w, v.w, sq_acc);
            if (p < 4) {
                cs0[p * 4 + 0] += v.x; cs0[p * 4 + 1] += v.y;
                cs0[p * 4 + 2] += v.z; cs0[p * 4 + 3] += v.w;
            } else {
                cs1[(p - 4) * 4 + 0] += v.x; cs1[(p - 4) * 4 + 1] += v.y;
                cs1[(p - 4) * 4 + 2] += v.z; cs1[(p - 4) * 4 + 3] += v.w;
            }
            rs += (v.x + v.y) + (v.z + v.w);
        }
#pragma unroll
        for (int o = 16; o > 0; o >>= 1) rs += __shfl_xor_sync(0xFFFFFFFFu, rs, o);
        if (lane == 0) r2_acc = fmaf(rs, rs, r2_acc);
    }

    // ============ cross-warp colsum reduce: 4 warps -> warp 0 ============
    // round 1: warps 2,3 publish; warps 0,1 accumulate
    if (w >= 2) {
        float* dp = &sbuf[(w - 2) * 1024];
#pragma unroll
        for (int p = 0; p < 4; p++) {
            reinterpret_cast<float4*>(dp)[p * 32 + lane] =
                make_float4(cs0[p*4+0], cs0[p*4+1], cs0[p*4+2], cs0[p*4+3]);
            reinterpret_cast<float4*>(dp)[(p + 4) * 32 + lane] =
                make_float4(cs1[p*4+0], cs1[p*4+1], cs1[p*4+2], cs1[p*4+3]);
        }
    }
    __syncthreads();
    if (w < 2) {
        const float* sp = &sbuf[w * 1024];
#pragma unroll
        for (int p = 0; p < 4; p++) {
            float4 u = reinterpret_cast<const float4*>(sp)[p * 32 + lane];
            cs0[p*4+0] += u.x; cs0[p*4+1] += u.y; cs0[p*4+2] += u.z; cs0[p*4+3] += u.w;
            float4 v = reinterpret_cast<const float4*>(sp)[(p + 4) * 32 + lane];
            cs1[p*4+0] += v.x; cs1[p*4+1] += v.y; cs1[p*4+2] += v.z; cs1[p*4+3] += v.w;
        }
    }
    __syncthreads();
    // round 2: warp 1 publishes; warp 0 accumulates
    if (w == 1) {
        float* dp = &sbuf[0];
#pragma unroll
        for (int p = 0; p < 4; p++) {
            reinterpret_cast<float4*>(dp)[p * 32 + lane] =
                make_float4(cs0[p*4+0], cs0[p*4+1], cs0[p*4+2], cs0[p*4+3]);
            reinterpret_cast<float4*>(dp)[(p + 4) * 32 + lane] =
                make_float4(cs1[p*4+0], cs1[p*4+1], cs1[p*4+2], cs1[p*4+3]);
        }
    }
    __syncthreads();
    if (w == 0) {
        const float* sp = &sbuf[0];
#pragma unroll
        for (int p = 0; p < 4; p++) {
            float4 u = reinterpret_cast<const float4*>(sp)[p * 32 + lane];
            cs0[p*4+0] += u.x; cs0[p*4+1] += u.y; cs0[p*4+2] += u.z; cs0[p*4+3] += u.w;
            float4 v = reinterpret_cast<const float4*>(sp)[(p + 4) * 32 + lane];
            cs1[p*4+0] += v.x; cs1[p*4+1] += v.y; cs1[p*4+2] += v.z; cs1[p*4+3] += v.w;
        }
    }

    // ==================== block totals of sq / r2 ====================
    {
        float s = sq_acc;
#pragma unroll
        for (int o = 16; o > 0; o >>= 1) s += __shfl_xor_sync(0xFFFFFFFFu, s, o);
        if (lane == 0) { red_a[w] = s; red_b[w] = r2_acc; }
    }
    __syncthreads();

    if (w == 0) {
        if (lane == 0) {
            g_sr[b][0] = red_a[0] + red_a[1] + red_a[2] + red_a[3];
            g_sr[b][1] = red_b[0] + red_b[1] + red_b[2] + red_b[3];
        }
        float4* dst = reinterpret_cast<float4*>(&g_cs[b][0]);
#pragma unroll
        for (int p = 0; p < 4; p++) {
            dst[p * 32 + lane] =
                make_float4(cs0[p*4+0], cs0[p*4+1], cs0[p*4+2], cs0[p*4+3]);
            dst[(p + 4) * 32 + lane] =
                make_float4(cs1[p*4+0], cs1[p*4+1], cs1[p*4+2], cs1[p*4+3]);
        }
    }

    // ============ elect last finisher for this t (no waiting) ============
    __syncthreads();                 // staging visible block-wide
    if (tid == 0) {
        s_final = false;
        __threadfence();
        unsigned old = atomicAdd(&g_tcnt[t], 1);
        s_comb = (old == NSEG - 1);
    }
    __syncthreads();

    if (s_comb) {
        __threadfence();             // acquire staged partials
        // combine NSEG colsum partials: thread -> 8 columns (2 float4)
        float4 f0 = make_float4(0.f, 0.f, 0.f, 0.f);
        float4 f1 = make_float4(0.f, 0.f, 0.f, 0.f);
#pragma unroll
        for (int s = 0; s < NSEG; s++) {
            const float4* p = reinterpret_cast<const float4*>(&g_cs[t * NSEG + s][tid * 8]);
            float4 u0 = __ldcg(p + 0);
            float4 u1 = __ldcg(p + 1);
            f0.x += u0.x; f0.y += u0.y; f0.z += u0.z; f0.w += u0.w;
            f1.x += u1.x; f1.y += u1.y; f1.z += u1.z; f1.w += u1.w;
        }
        float cs  = ((f0.x + f0.y) + (f0.z + f0.w)) + ((f1.x + f1.y) + (f1.z + f1.w));
        float cs2 = f0.x*f0.x + f0.y*f0.y + f0.z*f0.z + f0.w*f0.w
                  + f1.x*f1.x + f1.y*f1.y + f1.z*f1.z + f1.w*f1.w;
#pragma unroll
        for (int o = 16; o > 0; o >>= 1) {
            cs  += __shfl_xor_sync(0xFFFFFFFFu, cs,  o);
            cs2 += __shfl_xor_sync(0xFFFFFFFFu, cs2, o);
        }
        if (lane == 0) { red_a[w] = cs; red_b[w] = cs2; }
        __syncthreads();
        if (tid == 0) {
            float tcs  = red_a[0] + red_a[1] + red_a[2] + red_a[3];
            float tcs2 = red_b[0] + red_b[1] + red_b[2] + red_b[3];
            double sq_t = 0.0, r2_t = 0.0;
#pragma unroll
            for (int s = 0; s < NSEG; s++) {
                sq_t += (double)__ldcg(&g_sr[t * NSEG + s][0]);
                r2_t += (double)__ldcg(&g_sr[t * NSEG + s][1]);
            }
            g_t4[t][0] = sq_t;
            g_t4[t][1] = r2_t;
            g_t4[t][2] = (double)tcs2;
            g_t4[t][3] = (double)tcs * (double)tcs;
            g_tcnt[t] = 0;                       // self-reset
            __threadfence();
            unsigned o2 = atomicAdd(&g_gcnt, 1);
            if (o2 == T_DIM - 1) s_final = true;
        }
    }
    __syncthreads();

    // ================= last combiner computes the loss =================
    if (s_final && w == 0) {
        __threadfence();
        double a0 = 0, a1 = 0, a2 = 0, a3 = 0;
#pragma unroll
        for (int q = 0; q < 4; q++) {
            int tt = lane + 32 * q;
            a0 += __ldcg(&g_t4[tt][0]);
            a1 += __ldcg(&g_t4[tt][1]);
            a2 += __ldcg(&g_t4[tt][2]);
            a3 += __ldcg(&g_t4[tt][3]);
        }
#pragma unroll
        for (int o = 16; o > 0; o >>= 1) {
            a0 += __shfl_xor_sync(0xFFFFFFFFu, a0, o);
            a1 += __shfl_xor_sync(0xFFFFFFFFu, a1, o);
            a2 += __shfl_xor_sync(0xFFFFFFFFu, a2, o);
            a3 += __shfl_xor_sync(0xFFFFFFFFu, a3, o);
        }
        if (lane == 0) {
            const double c0 = (double)C0_DIM, c1 = (double)C1_DIM;
            const double cross  = a3 / (c0 * c1);
            const double intra  = a0 - a1 / c1;
            const double inter  = a1 / c1 - cross;
            const double dintra = a0 - a2 / c0;
            const double dinter = a2 / c0 - cross;
            out[0] = (float)(0.5 * (intra / inter + dintra / dinter) / (c0 * c1));
            g_gcnt = 0;                          // self-reset
        }
    }
}

extern "C" void kernel_launch(void* const* d_in, const int* in_sizes, int n_in,
                              void* d_out, int out_size) {
    const float* A = (const float*)d_in[0];
    float* out = (float*)d_out;
    (void)in_sizes; (void)n_in; (void)out_size;

    lcl_kernel<<<NBLK, 128>>>(A, out);
}